// round 1
// baseline (speedup 1.0000x reference)
#include <cuda_runtime.h>
#include <math.h>

#define BATCH 128
#define SEQ   1024
#define INP   7
#define HID   64
#define OUTD  500
#define MTOT  (BATCH*SEQ)   // 131072

// h outputs stored TRANSPOSED: g_hT[k][b*SEQ + t], k in [0,64)
// -> FC A-tile loads are coalesced along m and need no smem transpose.
__device__ float g_hT[(size_t)HID * MTOT];   // 33.5 MB scratch

// ---------------------------------------------------------------------------
// LSTM recurrence: one CTA per batch element, 256 threads.
// thread tid -> (h_idx = tid>>2, gate = tid&3); gate rows i,f,g,o = gate*64+h.
// W_hh row in registers (64 regs), h broadcast from smem (double buffered),
// gate exchange via 4-lane shuffles, ONE __syncthreads per timestep.
// ---------------------------------------------------------------------------
__global__ __launch_bounds__(256, 1)
void lstm_kernel(const float* __restrict__ x,
                 const float* __restrict__ W_ih,
                 const float* __restrict__ W_hh,
                 const float* __restrict__ b_ih,
                 const float* __restrict__ b_hh)
{
    __shared__ float xs[SEQ * INP];     // 28 KB: whole input sequence for this batch
    __shared__ float hbuf[2][HID];

    const int b    = blockIdx.x;
    const int tid  = threadIdx.x;
    const int hh   = tid >> 2;
    const int gate = tid & 3;
    const int row  = gate * HID + hh;   // row in [4H, *] weight matrices
    const int lane = tid & 31;
    const int lb   = lane & ~3;         // base lane of 4-lane gate group

    // stage x[b] into smem (coalesced float4)
    {
        const float4* src = (const float4*)(x + (size_t)b * SEQ * INP);
        float4* dst = (float4*)xs;
        #pragma unroll
        for (int i = 0; i < (SEQ*INP)/(4*256); ++i)   // 7 iters
            dst[tid + i*256] = src[tid + i*256];
    }

    // W_hh row -> registers
    float w[HID];
    {
        const float4* wr = (const float4*)(W_hh + (size_t)row * HID);
        #pragma unroll
        for (int i = 0; i < HID/4; ++i) {
            float4 v = wr[i];
            w[4*i+0]=v.x; w[4*i+1]=v.y; w[4*i+2]=v.z; w[4*i+3]=v.w;
        }
    }
    float wih[INP];
    #pragma unroll
    for (int i = 0; i < INP; ++i) wih[i] = W_ih[row*INP + i];
    const float bias = b_ih[row] + b_hh[row];

    if (tid < HID) hbuf[0][tid] = 0.0f;
    float c = 0.0f;
    __syncthreads();

    int cur = 0;
    for (int t = 0; t < SEQ; ++t) {
        // input contribution + bias
        const float* xt = xs + t*INP;
        float acc0 = bias;
        float acc1 = 0.0f;
        #pragma unroll
        for (int i = 0; i < INP; ++i) acc0 = fmaf(xt[i], wih[i], acc0);

        // h(t-1) @ W_hh^T  (broadcast LDS.128, two accumulator chains)
        const float4* hv = (const float4*)hbuf[cur];
        #pragma unroll
        for (int k = 0; k < HID/8; ++k) {
            float4 h0 = hv[2*k+0];
            float4 h1 = hv[2*k+1];
            acc0 = fmaf(h0.x, w[8*k+0], acc0); acc1 = fmaf(h0.y, w[8*k+1], acc1);
            acc0 = fmaf(h0.z, w[8*k+2], acc0); acc1 = fmaf(h0.w, w[8*k+3], acc1);
            acc0 = fmaf(h1.x, w[8*k+4], acc0); acc1 = fmaf(h1.y, w[8*k+5], acc1);
            acc0 = fmaf(h1.z, w[8*k+6], acc0); acc1 = fmaf(h1.w, w[8*k+7], acc1);
        }
        float pre = acc0 + acc1;

        // branchless activation: sigmoid for gates 0/1/3, tanh for gate 2
        float y = (gate == 2) ? 2.0f*pre : pre;
        float e = __expf(-y);
        float r = __fdividef(1.0f, 1.0f + e);
        float act = (gate == 2) ? (2.0f*r - 1.0f) : r;

        float ig = __shfl_sync(0xffffffffu, act, lb+0);
        float fg = __shfl_sync(0xffffffffu, act, lb+1);
        float gg = __shfl_sync(0xffffffffu, act, lb+2);
        float og = __shfl_sync(0xffffffffu, act, lb+3);

        if (gate == 0) {
            c = fmaf(fg, c, ig*gg);
            float e2 = __expf(-2.0f * c);
            float th = 2.0f * __fdividef(1.0f, 1.0f + e2) - 1.0f;
            float h = og * th;
            hbuf[cur ^ 1][hh] = h;
            g_hT[(size_t)hh * MTOT + (size_t)b * SEQ + t] = h;  // transposed store
        }
        __syncthreads();
        cur ^= 1;
    }
}

// ---------------------------------------------------------------------------
// FC: out[M=131072, N=500] = A[M,64] @ W_fc^T + b_fc
// CTA tile 128(M) x 64(N), 256 threads, thread tile 8x4.
// A^T staged in smem (no transpose needed thanks to g_hT layout);
// W_fc read from global (L1-resident, 128 KB total) via LDG.128.
// ---------------------------------------------------------------------------
#define FTM 128
#define FTN 64

__global__ __launch_bounds__(256)
void fc_kernel(const float* __restrict__ W_fc,
               const float* __restrict__ b_fc,
               float* __restrict__ out)
{
    __shared__ float As[HID][FTM];      // 32 KB, [k][m]

    const int tid  = threadIdx.x;
    const int tx   = tid & 15;          // n
    const int ty   = tid >> 4;          // m
    const int row0 = blockIdx.x * FTM;
    const int col0 = blockIdx.y * FTN;
    const int m0   = ty * 8;
    const int n0   = tx * 4;

    // load A^T tile: g_hT[k][row0 + m], fully coalesced, conflict-free STS.128
    #pragma unroll
    for (int l = 0; l < 8; ++l) {
        int fid = tid + l*256;          // 0..2047
        int k   = fid >> 5;
        int m4  = (fid & 31) * 4;
        float4 v = *(const float4*)(g_hT + (size_t)k*MTOT + row0 + m4);
        *(float4*)&As[k][m4] = v;
    }

    // 500 % 4 == 0 -> each thread's 4-wide N strip is all-in or all-out
    const bool nvalid = (col0 + n0) < OUTD;
    const float* bptr[4];
    #pragma unroll
    for (int j = 0; j < 4; ++j)
        bptr[j] = W_fc + (size_t)(nvalid ? (col0 + n0 + j) : 0) * HID;

    __syncthreads();

    float acc[8][4];
    #pragma unroll
    for (int mm = 0; mm < 8; ++mm)
        #pragma unroll
        for (int nn = 0; nn < 4; ++nn) acc[mm][nn] = 0.0f;

    #pragma unroll 4
    for (int k0 = 0; k0 < HID; k0 += 4) {
        float4 b4[4];
        #pragma unroll
        for (int j = 0; j < 4; ++j)
            b4[j] = *(const float4*)(bptr[j] + k0);   // LDG.128, L1-hot

        #pragma unroll
        for (int kk = 0; kk < 4; ++kk) {
            float4 a0 = *(const float4*)&As[k0+kk][m0];
            float4 a1 = *(const float4*)&As[k0+kk][m0+4];
            float a[8] = {a0.x,a0.y,a0.z,a0.w,a1.x,a1.y,a1.z,a1.w};
            float bb[4];
            #pragma unroll
            for (int j = 0; j < 4; ++j)
                bb[j] = ((const float*)&b4[j])[kk];
            #pragma unroll
            for (int mm = 0; mm < 8; ++mm)
                #pragma unroll
                for (int nn = 0; nn < 4; ++nn)
                    acc[mm][nn] = fmaf(a[mm], bb[nn], acc[mm][nn]);
        }
    }

    if (!nvalid) return;

    float4 bias = *(const float4*)(b_fc + col0 + n0);  // aligned: (col0+n0)%4==0
    #pragma unroll
    for (int mm = 0; mm < 8; ++mm) {
        int r = row0 + m0 + mm;
        float4 o;
        o.x = acc[mm][0] + bias.x;
        o.y = acc[mm][1] + bias.y;
        o.z = acc[mm][2] + bias.z;
        o.w = acc[mm][3] + bias.w;
        // out row stride 500 floats: 500%4==0 -> 16B aligned STG.128
        *(float4*)(out + (size_t)r * OUTD + col0 + n0) = o;
    }
}

extern "C" void kernel_launch(void* const* d_in, const int* in_sizes, int n_in,
                              void* d_out, int out_size)
{
    const float* x    = (const float*)d_in[0];
    const float* W_ih = (const float*)d_in[1];
    const float* W_hh = (const float*)d_in[2];
    const float* b_ih = (const float*)d_in[3];
    const float* b_hh = (const float*)d_in[4];
    const float* W_fc = (const float*)d_in[5];
    const float* b_fc = (const float*)d_in[6];
    float* out = (float*)d_out;

    lstm_kernel<<<BATCH, 256>>>(x, W_ih, W_hh, b_ih, b_hh);
    fc_kernel<<<dim3(MTOT/FTM, (OUTD + FTN - 1)/FTN), 256>>>(W_fc, b_fc, out);
}

// round 2
// speedup vs baseline: 1.4936x; 1.4936x over previous
#include <cuda_runtime.h>
#include <math.h>

#define BATCH 128
#define SEQ   1024
#define INP   7
#define HID   64
#define OUTD  500
#define MTOT  (BATCH*SEQ)   // 131072

typedef unsigned long long u64;

__device__ float g_hT[(size_t)HID * MTOT];   // h transposed: g_hT[k][b*SEQ+t]

// ---- f32x2 packed helpers (FFMA2 path, sm_103a) ----
__device__ __forceinline__ u64 pack2(float a, float b) {
    u64 r;
    asm("mov.b64 %0, {%1, %2};" : "=l"(r)
        : "r"(__float_as_uint(a)), "r"(__float_as_uint(b)));
    return r;
}
__device__ __forceinline__ u64 ffma2(u64 a, u64 b, u64 c) {
    u64 d;
    asm("fma.rn.f32x2 %0, %1, %2, %3;" : "=l"(d) : "l"(a), "l"(b), "l"(c));
    return d;
}
__device__ __forceinline__ u64 fadd2(u64 a, u64 b) {
    u64 d;
    asm("add.rn.f32x2 %0, %1, %2;" : "=l"(d) : "l"(a), "l"(b));
    return d;
}
__device__ __forceinline__ void unpack2(u64 v, float& lo, float& hi) {
    unsigned int l, h;
    asm("mov.b64 {%0, %1}, %2;" : "=r"(l), "=r"(h) : "l"(v));
    lo = __uint_as_float(l); hi = __uint_as_float(h);
}

// ---------------------------------------------------------------------------
// LSTM recurrence: one CTA per batch element, 256 threads.
// thread -> (hh = tid>>2, gate = tid&3). W_hh row packed in registers (FFMA2),
// h broadcast from smem (double buffered), gate exchange via 4-lane shuffles,
// ONE __syncthreads per step. Next-step x-contribution hoisted before barrier.
// ---------------------------------------------------------------------------
__global__ __launch_bounds__(256, 1)
void lstm_kernel(const float* __restrict__ x,
                 const float* __restrict__ W_ih,
                 const float* __restrict__ W_hh,
                 const float* __restrict__ b_ih,
                 const float* __restrict__ b_hh)
{
    __shared__ float xs[SEQ * INP];                 // 28 KB
    __shared__ __align__(16) float hbuf[2][HID];

    const int b    = blockIdx.x;
    const int tid  = threadIdx.x;
    const int hh   = tid >> 2;
    const int gate = tid & 3;
    const int row  = gate * HID + hh;
    const int lane = tid & 31;
    const int lb   = lane & ~3;

    // stage x[b] (coalesced float4)
    {
        const float4* src = (const float4*)(x + (size_t)b * SEQ * INP);
        float4* dst = (float4*)xs;
        #pragma unroll
        for (int i = 0; i < (SEQ*INP)/(4*256); ++i)
            dst[tid + i*256] = src[tid + i*256];
    }

    // W_hh row -> packed registers (32 x f32x2)
    u64 w2[HID/2];
    {
        const ulonglong2* wr = (const ulonglong2*)(W_hh + (size_t)row * HID);
        #pragma unroll
        for (int i = 0; i < HID/4; ++i) {
            ulonglong2 v = wr[i];
            w2[2*i+0] = v.x; w2[2*i+1] = v.y;
        }
    }
    float wih[INP];
    #pragma unroll
    for (int i = 0; i < INP; ++i) wih[i] = W_ih[row*INP + i];
    const float bias = b_ih[row] + b_hh[row];

    if (tid < HID) hbuf[0][tid] = 0.0f;
    float c = 0.0f;
    __syncthreads();

    // x contribution for t=0
    float xacc = bias;
    #pragma unroll
    for (int i = 0; i < INP; ++i) xacc = fmaf(xs[i], wih[i], xacc);

    int cur = 0;
    for (int t = 0; t < SEQ; ++t) {
        // h(t-1) @ W_hh^T  : 4 FFMA2 chains of depth 8
        const ulonglong2* hv = (const ulonglong2*)hbuf[cur];
        u64 a0 = 0ull, a1 = 0ull, a2 = 0ull, a3 = 0ull;
        #pragma unroll
        for (int j = 0; j < 8; ++j) {
            ulonglong2 h0 = hv[2*j+0];
            ulonglong2 h1 = hv[2*j+1];
            a0 = ffma2(h0.x, w2[4*j+0], a0);
            a1 = ffma2(h0.y, w2[4*j+1], a1);
            a2 = ffma2(h1.x, w2[4*j+2], a2);
            a3 = ffma2(h1.y, w2[4*j+3], a3);
        }
        u64 s2 = fadd2(fadd2(a0, a1), fadd2(a2, a3));
        float slo, shi; unpack2(s2, slo, shi);
        float pre = xacc + slo + shi;

        // activation: sigmoid (gates 0,1,3), tanh (gate 2)
        float y = (gate == 2) ? 2.0f*pre : pre;
        float e = __expf(-y);
        float r = __fdividef(1.0f, 1.0f + e);
        float act = (gate == 2) ? (2.0f*r - 1.0f) : r;

        float ig = __shfl_sync(0xffffffffu, act, lb+0);
        float fg = __shfl_sync(0xffffffffu, act, lb+1);
        float gg = __shfl_sync(0xffffffffu, act, lb+2);
        float og = __shfl_sync(0xffffffffu, act, lb+3);

        // all 4 gate threads compute c,h redundantly (no divergence)
        c = fmaf(fg, c, ig*gg);
        float e2 = __expf(-2.0f * c);
        float th = 2.0f * __fdividef(1.0f, 1.0f + e2) - 1.0f;
        float h = og * th;
        if (gate == 0) {
            hbuf[cur ^ 1][hh] = h;
            g_hT[(size_t)hh * MTOT + (size_t)b * SEQ + t] = h;
        }

        // hoist next-step x contribution BEFORE the barrier
        int tn = (t + 1 < SEQ) ? t + 1 : 0;
        const float* xt = xs + tn*INP;
        float xn = bias;
        #pragma unroll
        for (int i = 0; i < INP; ++i) xn = fmaf(xt[i], wih[i], xn);
        xacc = xn;

        __syncthreads();
        cur ^= 1;
    }
}

// ---------------------------------------------------------------------------
// FC: out[131072, 500] = A[M,64] @ W_fc^T + b_fc
// CTA: 128m x 128n tile, 512 threads, thread tile 8m x 4n, FFMA2 accumulators.
// W_fc tile staged in smem [k][n] (transposed on load), reused across
// MLOOP=4 m-tiles per CTA. A staged from g_hT (already [k][m]) -> zero
// transpose cost, all smem traffic conflict-free/broadcast.
// ---------------------------------------------------------------------------
#define FTM 128
#define FTN 128
#define MLOOP 4
#define FCT 512

__global__ __launch_bounds__(FCT, 1)
void fc_kernel(const float* __restrict__ W_fc,
               const float* __restrict__ b_fc,
               float* __restrict__ out)
{
    __shared__ float As[HID][FTM];      // 32 KB
    __shared__ float Bs[HID][FTN];      // 32 KB

    const int tid  = threadIdx.x;
    const int lane = tid & 31;
    const int warp = tid >> 5;
    const int tx   = tid & 31;          // n: strip of 4
    const int ty   = tid >> 5;          // m: strip of 8
    const int n0   = tx * 4;
    const int m0   = ty * 8;
    const int col0 = blockIdx.y * FTN;

    // ---- load B tile: Bs[k][n] = W_fc[col0+n][k] ----
    // warp covers 8 n x 4 kf (float4): gmem 64B chunks, STS 4-way max conflict
    #pragma unroll
    for (int l = 0; l < 4; ++l) {
        int wl = warp + l*16;                       // 0..63
        int n  = (wl & 15) * 8 + (lane >> 2);       // 0..127
        int kf = (wl >> 4) * 4 + (lane & 3);        // 0..15 (float4 idx in k)
        int r  = col0 + n;
        float4 v = make_float4(0.f,0.f,0.f,0.f);
        if (r < OUTD) v = *(const float4*)(W_fc + (size_t)r * HID + kf*4);
        Bs[kf*4+0][n] = v.x;
        Bs[kf*4+1][n] = v.y;
        Bs[kf*4+2][n] = v.z;
        Bs[kf*4+3][n] = v.w;
    }

    const bool nvalid = (col0 + n0) < OUTD;  // 500%4==0: strip all-in/all-out

    for (int mt = 0; mt < MLOOP; ++mt) {
        const int row0 = (blockIdx.x * MLOOP + mt) * FTM;

        __syncthreads();   // prev compute done (and B stores visible on mt=0)
        // ---- load A tile: As[k][m] from g_hT (coalesced, conflict-free) ----
        #pragma unroll
        for (int l = 0; l < 4; ++l) {
            int fid = tid + l*FCT;                  // 0..2047
            int k   = fid >> 5;
            int m4  = (fid & 31) * 4;
            float4 v = *(const float4*)(g_hT + (size_t)k*MTOT + row0 + m4);
            *(float4*)&As[k][m4] = v;
        }
        __syncthreads();

        u64 acc[4][4];
        #pragma unroll
        for (int mm = 0; mm < 4; ++mm)
            #pragma unroll
            for (int nn = 0; nn < 4; ++nn) acc[mm][nn] = 0ull;

        const float* asr = &As[0][m0];
        const float* bsr = &Bs[0][n0];
        #pragma unroll 4
        for (int k = 0; k < HID; ++k) {
            ulonglong2 aA = *(const ulonglong2*)(asr);      // (m0,m0+1),(m0+2,m0+3)
            ulonglong2 aB = *(const ulonglong2*)(asr + 4);  // (m0+4..m0+7)
            float4 bv = *(const float4*)(bsr);
            asr += FTM; bsr += FTN;
            u64 ap0 = aA.x, ap1 = aA.y, ap2 = aB.x, ap3 = aB.y;
            u64 b2[4];
            b2[0] = pack2(bv.x, bv.x);
            b2[1] = pack2(bv.y, bv.y);
            b2[2] = pack2(bv.z, bv.z);
            b2[3] = pack2(bv.w, bv.w);
            #pragma unroll
            for (int nn = 0; nn < 4; ++nn) {
                acc[0][nn] = ffma2(ap0, b2[nn], acc[0][nn]);
                acc[1][nn] = ffma2(ap1, b2[nn], acc[1][nn]);
                acc[2][nn] = ffma2(ap2, b2[nn], acc[2][nn]);
                acc[3][nn] = ffma2(ap3, b2[nn], acc[3][nn]);
            }
        }

        if (nvalid) {
            float4 bias = *(const float4*)(b_fc + col0 + n0);
            const float bb[4] = {bias.x, bias.y, bias.z, bias.w};
            #pragma unroll
            for (int mm = 0; mm < 4; ++mm) {
                float lo[4], hi[4];
                #pragma unroll
                for (int nn = 0; nn < 4; ++nn) unpack2(acc[mm][nn], lo[nn], hi[nn]);
                int r0 = row0 + m0 + 2*mm;
                float4 o0, o1;
                o0.x = lo[0]+bb[0]; o0.y = lo[1]+bb[1]; o0.z = lo[2]+bb[2]; o0.w = lo[3]+bb[3];
                o1.x = hi[0]+bb[0]; o1.y = hi[1]+bb[1]; o1.z = hi[2]+bb[2]; o1.w = hi[3]+bb[3];
                *(float4*)(out + (size_t)r0     * OUTD + col0 + n0) = o0;
                *(float4*)(out + (size_t)(r0+1) * OUTD + col0 + n0) = o1;
            }
        }
    }
}

extern "C" void kernel_launch(void* const* d_in, const int* in_sizes, int n_in,
                              void* d_out, int out_size)
{
    const float* x    = (const float*)d_in[0];
    const float* W_ih = (const float*)d_in[1];
    const float* W_hh = (const float*)d_in[2];
    const float* b_ih = (const float*)d_in[3];
    const float* b_hh = (const float*)d_in[4];
    const float* W_fc = (const float*)d_in[5];
    const float* b_fc = (const float*)d_in[6];
    float* out = (float*)d_out;

    lstm_kernel<<<BATCH, 256>>>(x, W_ih, W_hh, b_ih, b_hh);
    fc_kernel<<<dim3(MTOT/(FTM*MLOOP), (OUTD + FTN - 1)/FTN), FCT>>>(W_fc, b_fc, out);
}

// round 3
// speedup vs baseline: 1.6103x; 1.0781x over previous
#include <cuda_runtime.h>
#include <math.h>

#define BATCH 128
#define SEQ   1024
#define INP   7
#define HID   64
#define OUTD  500
#define MTOT  (BATCH*SEQ)   // 131072

typedef unsigned long long u64;

__device__ float g_hT[(size_t)HID * MTOT];   // h transposed: g_hT[k][b*SEQ+t]

// ---- f32x2 packed helpers ----
__device__ __forceinline__ u64 pack2(float a, float b) {
    u64 r;
    asm("mov.b64 %0, {%1, %2};" : "=l"(r)
        : "r"(__float_as_uint(a)), "r"(__float_as_uint(b)));
    return r;
}
__device__ __forceinline__ u64 ffma2(u64 a, u64 b, u64 c) {
    u64 d;
    asm("fma.rn.f32x2 %0, %1, %2, %3;" : "=l"(d) : "l"(a), "l"(b), "l"(c));
    return d;
}
__device__ __forceinline__ u64 fadd2(u64 a, u64 b) {
    u64 d;
    asm("add.rn.f32x2 %0, %1, %2;" : "=l"(d) : "l"(a), "l"(b));
    return d;
}
__device__ __forceinline__ void unpack2(u64 v, float& lo, float& hi) {
    unsigned int l, h;
    asm("mov.b64 {%0, %1}, %2;" : "=r"(l), "=r"(h) : "l"(v));
    lo = __uint_as_float(l); hi = __uint_as_float(h);
}
__device__ __forceinline__ float tanhf_fast(float x) {
    float y;
    asm("tanh.approx.f32 %0, %1;" : "=f"(y) : "f"(x));
    return y;
}

// ---------------------------------------------------------------------------
// LSTM recurrence: one CTA per batch element, 256 threads.
// thread -> (hh = tid>>2, gate = tid&3). W_hh row packed in regs (FFMA2),
// 8 chains of depth 4, tanh.approx activations, h staged in smem and dumped
// to g_hT as coalesced float4 every 16 steps (double-buffered window).
// ---------------------------------------------------------------------------
#define HSP 20   // hstage row pad (floats): conflict-free + float4 aligned

__global__ __launch_bounds__(256, 1)
void lstm_kernel(const float* __restrict__ x,
                 const float* __restrict__ W_ih,
                 const float* __restrict__ W_hh,
                 const float* __restrict__ b_ih,
                 const float* __restrict__ b_hh)
{
    __shared__ float xs[SEQ * INP];                 // 28 KB
    __shared__ __align__(16) float hbuf[2][HID];
    __shared__ __align__(16) float hstage[2][HID][HSP];  // 10 KB

    const int b    = blockIdx.x;
    const int tid  = threadIdx.x;
    const int hh   = tid >> 2;
    const int gate = tid & 3;
    const int row  = gate * HID + hh;
    const int lane = tid & 31;
    const int lb   = lane & ~3;

    // stage x[b] (coalesced float4)
    {
        const float4* src = (const float4*)(x + (size_t)b * SEQ * INP);
        float4* dst = (float4*)xs;
        #pragma unroll
        for (int i = 0; i < (SEQ*INP)/(4*256); ++i)
            dst[tid + i*256] = src[tid + i*256];
    }

    // W_hh row -> packed registers (32 x f32x2)
    u64 w2[HID/2];
    {
        const ulonglong2* wr = (const ulonglong2*)(W_hh + (size_t)row * HID);
        #pragma unroll
        for (int i = 0; i < HID/4; ++i) {
            ulonglong2 v = wr[i];
            w2[2*i+0] = v.x; w2[2*i+1] = v.y;
        }
    }
    float wih[INP];
    #pragma unroll
    for (int i = 0; i < INP; ++i) wih[i] = W_ih[row*INP + i];
    const float bias = b_ih[row] + b_hh[row];

    // activation constants: gates 0,1,3 -> sigmoid = 0.5*tanh(0.5x)+0.5
    //                       gate 2     -> tanh(x) = 1.0*tanh(1.0x)+0.0
    const float sc  = (gate == 2) ? 1.0f : 0.5f;
    const float off = (gate == 2) ? 0.0f : 0.5f;

    if (tid < HID) hbuf[0][tid] = 0.0f;
    float c = 0.0f;
    __syncthreads();

    // x contribution for t=0
    float xacc = bias;
    #pragma unroll
    for (int i = 0; i < INP; ++i) xacc = fmaf(xs[i], wih[i], xacc);

    int cur = 0;
    for (int t = 0; t < SEQ; ++t) {
        // h(t-1) @ W_hh^T : 8 FFMA2 chains of depth 4
        const ulonglong2* hv = (const ulonglong2*)hbuf[cur];
        u64 a[8];
        #pragma unroll
        for (int i = 0; i < 8; ++i) a[i] = 0ull;
        #pragma unroll
        for (int j = 0; j < 4; ++j) {
            ulonglong2 h0 = hv[4*j+0];
            ulonglong2 h1 = hv[4*j+1];
            ulonglong2 h2 = hv[4*j+2];
            ulonglong2 h3 = hv[4*j+3];
            a[0] = ffma2(h0.x, w2[8*j+0], a[0]);
            a[1] = ffma2(h0.y, w2[8*j+1], a[1]);
            a[2] = ffma2(h1.x, w2[8*j+2], a[2]);
            a[3] = ffma2(h1.y, w2[8*j+3], a[3]);
            a[4] = ffma2(h2.x, w2[8*j+4], a[4]);
            a[5] = ffma2(h2.y, w2[8*j+5], a[5]);
            a[6] = ffma2(h3.x, w2[8*j+6], a[6]);
            a[7] = ffma2(h3.y, w2[8*j+7], a[7]);
        }
        u64 s0 = fadd2(a[0], a[1]);
        u64 s1 = fadd2(a[2], a[3]);
        u64 s2 = fadd2(a[4], a[5]);
        u64 s3 = fadd2(a[6], a[7]);
        u64 s  = fadd2(fadd2(s0, s1), fadd2(s2, s3));
        float slo, shi; unpack2(s, slo, shi);
        float pre = xacc + slo + shi;

        // single-MUFU activation
        float act = fmaf(sc, tanhf_fast(sc * pre), off);

        float ig = __shfl_sync(0xffffffffu, act, lb+0);
        float fg = __shfl_sync(0xffffffffu, act, lb+1);
        float gg = __shfl_sync(0xffffffffu, act, lb+2);
        float og = __shfl_sync(0xffffffffu, act, lb+3);

        c = fmaf(fg, c, ig*gg);
        float h = og * tanhf_fast(c);
        if (gate == 0) {
            hbuf[cur ^ 1][hh] = h;
            hstage[(t >> 4) & 1][hh][t & 15] = h;
        }

        // next-step x contribution (off critical path, before barrier)
        int tn = (t + 1 < SEQ) ? t + 1 : 0;
        const float* xt = xs + tn*INP;
        float xn = bias;
        #pragma unroll
        for (int i = 0; i < INP; ++i) xn = fmaf(xt[i], wih[i], xn);
        xacc = xn;

        __syncthreads();
        cur ^= 1;

        // coalesced dump of 16-step h window (double-buffered: no race)
        if ((t & 15) == 15) {
            int wsel = (t >> 4) & 1;
            int k = tid >> 2;
            int j = (tid & 3) * 4;
            const float* hp = &hstage[wsel][k][j];
            float4 v = make_float4(hp[0], hp[1], hp[2], hp[3]);
            *(float4*)(g_hT + (size_t)k*MTOT + (size_t)b*SEQ + (t - 15) + j) = v;
        }
    }
}

// ---------------------------------------------------------------------------
// FC: out[131072, 500] = A[M,64] @ W_fc^T + b_fc
// CTA 128m x 128n, 512 threads, thread tile 8m x 4n, FFMA2 accumulators.
// B tile in smem, reused across MLOOP=8 m-tiles; next A tile register-
// prefetched during compute to hide global latency.
// ---------------------------------------------------------------------------
#define FTM 128
#define FTN 128
#define MLOOP 8
#define FCT 512

__global__ __launch_bounds__(FCT, 1)
void fc_kernel(const float* __restrict__ W_fc,
               const float* __restrict__ b_fc,
               float* __restrict__ out)
{
    __shared__ float As[HID][FTM];      // 32 KB
    __shared__ float Bs[HID][FTN];      // 32 KB

    const int tid  = threadIdx.x;
    const int lane = tid & 31;
    const int warp = tid >> 5;
    const int tx   = tid & 31;          // n: strip of 4
    const int ty   = tid >> 5;          // m: strip of 8
    const int n0   = tx * 4;
    const int m0   = ty * 8;
    const int col0 = blockIdx.y * FTN;

    // ---- load B tile: Bs[k][n] = W_fc[col0+n][k] ----
    #pragma unroll
    for (int l = 0; l < 4; ++l) {
        int wl = warp + l*16;                       // 0..63
        int n  = (wl & 15) * 8 + (lane >> 2);       // 0..127
        int kf = (wl >> 4) * 4 + (lane & 3);        // 0..15
        int r  = col0 + n;
        float4 v = make_float4(0.f,0.f,0.f,0.f);
        if (r < OUTD) v = *(const float4*)(W_fc + (size_t)r * HID + kf*4);
        Bs[kf*4+0][n] = v.x;
        Bs[kf*4+1][n] = v.y;
        Bs[kf*4+2][n] = v.z;
        Bs[kf*4+3][n] = v.w;
    }

    const bool nvalid = (col0 + n0) < OUTD;

    // A-tile gather indices (thread-invariant across mt)
    const int ak[4] = { (tid)       >> 5, (tid+FCT)   >> 5,
                        (tid+2*FCT) >> 5, (tid+3*FCT) >> 5 };
    const int am[4] = { (tid & 31)*4, (tid & 31)*4, (tid & 31)*4, (tid & 31)*4 };

    // prefetch A tile for mt=0
    float4 pre[4];
    {
        const int row0 = blockIdx.x * MLOOP * FTM;
        #pragma unroll
        for (int l = 0; l < 4; ++l)
            pre[l] = *(const float4*)(g_hT + (size_t)ak[l]*MTOT + row0 + am[l]);
    }

    for (int mt = 0; mt < MLOOP; ++mt) {
        const int row0 = (blockIdx.x * MLOOP + mt) * FTM;

        __syncthreads();   // prev compute done / B stores visible
        #pragma unroll
        for (int l = 0; l < 4; ++l)
            *(float4*)&As[ak[l]][am[l]] = pre[l];
        __syncthreads();

        // prefetch next A tile (overlaps with compute)
        if (mt + 1 < MLOOP) {
            const int rn = row0 + FTM;
            #pragma unroll
            for (int l = 0; l < 4; ++l)
                pre[l] = *(const float4*)(g_hT + (size_t)ak[l]*MTOT + rn + am[l]);
        }

        u64 acc[4][4];
        #pragma unroll
        for (int mm = 0; mm < 4; ++mm)
            #pragma unroll
            for (int nn = 0; nn < 4; ++nn) acc[mm][nn] = 0ull;

        const float* asr = &As[0][m0];
        const float* bsr = &Bs[0][n0];
        #pragma unroll 8
        for (int k = 0; k < HID; ++k) {
            ulonglong2 aA = *(const ulonglong2*)(asr);
            ulonglong2 aB = *(const ulonglong2*)(asr + 4);
            float4 bv = *(const float4*)(bsr);
            asr += FTM; bsr += FTN;
            u64 b2[4];
            b2[0] = pack2(bv.x, bv.x);
            b2[1] = pack2(bv.y, bv.y);
            b2[2] = pack2(bv.z, bv.z);
            b2[3] = pack2(bv.w, bv.w);
            #pragma unroll
            for (int nn = 0; nn < 4; ++nn) {
                acc[0][nn] = ffma2(aA.x, b2[nn], acc[0][nn]);
                acc[1][nn] = ffma2(aA.y, b2[nn], acc[1][nn]);
                acc[2][nn] = ffma2(aB.x, b2[nn], acc[2][nn]);
                acc[3][nn] = ffma2(aB.y, b2[nn], acc[3][nn]);
            }
        }

        if (nvalid) {
            float4 bias = *(const float4*)(b_fc + col0 + n0);
            const float bb[4] = {bias.x, bias.y, bias.z, bias.w};
            #pragma unroll
            for (int mm = 0; mm < 4; ++mm) {
                float lo[4], hi[4];
                #pragma unroll
                for (int nn = 0; nn < 4; ++nn) unpack2(acc[mm][nn], lo[nn], hi[nn]);
                int r0 = row0 + m0 + 2*mm;
                float4 o0, o1;
                o0.x = lo[0]+bb[0]; o0.y = lo[1]+bb[1]; o0.z = lo[2]+bb[2]; o0.w = lo[3]+bb[3];
                o1.x = hi[0]+bb[0]; o1.y = hi[1]+bb[1]; o1.z = hi[2]+bb[2]; o1.w = hi[3]+bb[3];
                *(float4*)(out + (size_t)r0     * OUTD + col0 + n0) = o0;
                *(float4*)(out + (size_t)(r0+1) * OUTD + col0 + n0) = o1;
            }
        }
    }
}

extern "C" void kernel_launch(void* const* d_in, const int* in_sizes, int n_in,
                              void* d_out, int out_size)
{
    const float* x    = (const float*)d_in[0];
    const float* W_ih = (const float*)d_in[1];
    const float* W_hh = (const float*)d_in[2];
    const float* b_ih = (const float*)d_in[3];
    const float* b_hh = (const float*)d_in[4];
    const float* W_fc = (const float*)d_in[5];
    const float* b_fc = (const float*)d_in[6];
    float* out = (float*)d_out;

    lstm_kernel<<<BATCH, 256>>>(x, W_ih, W_hh, b_ih, b_hh);
    fc_kernel<<<dim3(MTOT/(FTM*MLOOP), (OUTD + FTN - 1)/FTN), FCT>>>(W_fc, b_fc, out);
}